// round 1
// baseline (speedup 1.0000x reference)
#include <cuda_runtime.h>
#include <math.h>

// ---------------- problem constants ----------------
#define S_    2048
#define NIMG_ 4
#define LI_   512
#define H_    16
#define DH_   64
#define DIM_  1024
#define BOT_  256
#define KSEL_ 256
#define IH_   4
#define ID_   16
#define GH_   8
#define NBUCK_ 129

// ---------------- scratch (device globals; no runtime alloc) ----------------
__device__ float    g_tmp1[S_ * BOT_];                       // 2 MB
__device__ float    g_qkv [S_ * 3 * DIM_];                   // 24 MB (q|k|v interleaved per token)
__device__ float    g_qI  [S_ * 128];                        // 1 MB
__device__ float    g_kI  [S_ * 128];                        // 1 MB
__device__ float    g_scores[NIMG_ * LI_ * LI_];             // 4 MB
__device__ unsigned g_selmask[S_ * 16];                      // 128 KB (512-bit mask per query)
__device__ float    g_sbuf[(size_t)NIMG_ * H_ * LI_ * LI_];  // 67 MB attention logits/probs
__device__ float    g_attout[S_ * DIM_];                     // 8 MB
__device__ float    g_tmp2[S_ * BOT_];                       // 2 MB

// ======================================================================
// Generic tiled GEMM bodies. 256 threads, 64x64 output tile, BK=16,
// 4x4 register micro-tile per thread. All M,N multiples of 64; K of 16.
// gemm_tn: C[m][n] = sum_k A[m*lda+k] * B[n*ldb+k]   (both k-contiguous)
// gemm_nn: C[m][n] = sum_k A[m*lda+k] * B[k*ldb+n]   (B n-contiguous)
// ======================================================================
#define SMS 68  // smem row stride (floats); 68*4=272 bytes, 16B-aligned, conflict-free

__device__ __forceinline__ void gemm_tn_body(
    const float* __restrict__ A, int lda,
    const float* __restrict__ B, int ldb,
    float* __restrict__ C, int ldc, int K,
    const float* __restrict__ bias,
    const float* __restrict__ scaler)
{
    __shared__ float As[16 * SMS];
    __shared__ float Bs[16 * SMS];
    const int t  = threadIdx.x;
    const int tx = t & 15, ty = t >> 4;
    const int m0 = blockIdx.y * 64, n0 = blockIdx.x * 64;
    const int lm = t >> 2;           // 0..63
    const int lk = (t & 3) << 2;     // 0,4,8,12
    const float* Ap = A + (size_t)(m0 + lm) * lda + lk;
    const float* Bp = B + (size_t)(n0 + lm) * ldb + lk;
    float acc[4][4] = {};
    for (int k0 = 0; k0 < K; k0 += 16) {
        float4 av = *(const float4*)(Ap + k0);
        float4 bv = *(const float4*)(Bp + k0);
        __syncthreads();
        As[(lk+0)*SMS+lm]=av.x; As[(lk+1)*SMS+lm]=av.y;
        As[(lk+2)*SMS+lm]=av.z; As[(lk+3)*SMS+lm]=av.w;
        Bs[(lk+0)*SMS+lm]=bv.x; Bs[(lk+1)*SMS+lm]=bv.y;
        Bs[(lk+2)*SMS+lm]=bv.z; Bs[(lk+3)*SMS+lm]=bv.w;
        __syncthreads();
        #pragma unroll
        for (int kk = 0; kk < 16; kk++) {
            float4 a = *(const float4*)&As[kk*SMS + (ty<<2)];
            float4 b = *(const float4*)&Bs[kk*SMS + (tx<<2)];
            float ar[4] = {a.x,a.y,a.z,a.w};
            float br[4] = {b.x,b.y,b.z,b.w};
            #pragma unroll
            for (int i=0;i<4;i++)
                #pragma unroll
                for (int j=0;j<4;j++)
                    acc[i][j] = fmaf(ar[i], br[j], acc[i][j]);
        }
    }
    float sc = scaler ? *scaler : 1.f;
    #pragma unroll
    for (int i=0;i<4;i++){
        int m = m0 + (ty<<2) + i;
        #pragma unroll
        for (int j=0;j<4;j++){
            int n = n0 + (tx<<2) + j;
            float v = acc[i][j];
            if (bias) v += bias[n];
            C[(size_t)m*ldc + n] = v * sc;
        }
    }
}

__device__ __forceinline__ void gemm_nn_body(
    const float* __restrict__ A, int lda,
    const float* __restrict__ B, int ldb,
    float* __restrict__ C, int ldc, int K)
{
    __shared__ float As[16 * SMS];
    __shared__ float Bs[16 * SMS];
    const int t  = threadIdx.x;
    const int tx = t & 15, ty = t >> 4;
    const int m0 = blockIdx.y * 64, n0 = blockIdx.x * 64;
    const int lm  = t >> 2;
    const int lk  = (t & 3) << 2;
    const int lkB = t >> 4;          // 0..15
    const int lnB = (t & 15) << 2;   // 0..60
    const float* Ap = A + (size_t)(m0 + lm) * lda + lk;
    const float* Bp = B + (size_t)lkB * ldb + n0 + lnB;
    float acc[4][4] = {};
    for (int k0 = 0; k0 < K; k0 += 16) {
        float4 av = *(const float4*)(Ap + k0);
        float4 bv = *(const float4*)(Bp + (size_t)k0 * ldb);
        __syncthreads();
        As[(lk+0)*SMS+lm]=av.x; As[(lk+1)*SMS+lm]=av.y;
        As[(lk+2)*SMS+lm]=av.z; As[(lk+3)*SMS+lm]=av.w;
        *(float4*)&Bs[lkB*SMS + lnB] = bv;
        __syncthreads();
        #pragma unroll
        for (int kk = 0; kk < 16; kk++) {
            float4 a = *(const float4*)&As[kk*SMS + (ty<<2)];
            float4 b = *(const float4*)&Bs[kk*SMS + (tx<<2)];
            float ar[4] = {a.x,a.y,a.z,a.w};
            float br[4] = {b.x,b.y,b.z,b.w};
            #pragma unroll
            for (int i=0;i<4;i++)
                #pragma unroll
                for (int j=0;j<4;j++)
                    acc[i][j] = fmaf(ar[i], br[j], acc[i][j]);
        }
    }
    #pragma unroll
    for (int i=0;i<4;i++){
        int m = m0 + (ty<<2) + i;
        #pragma unroll
        for (int j=0;j<4;j++){
            int n = n0 + (tx<<2) + j;
            C[(size_t)m*ldc + n] = acc[i][j];
        }
    }
}

__global__ void k_gemm_tn(const float* __restrict__ A, int lda,
                          const float* __restrict__ B, int ldb,
                          float* __restrict__ C, int ldc, int K,
                          const float* __restrict__ bias,
                          const float* __restrict__ scaler)
{
    gemm_tn_body(A, lda, B, ldb, C, ldc, K, bias, scaler);
}

// Batched QK^T per (image, head): logits -> g_sbuf. K-dim = DH = 64.
__global__ void k_qk()
{
    int z = blockIdx.z, img = z >> 4, h = z & 15;
    const float* A = g_qkv + (size_t)img * LI_ * 3072 + h * 64;         // q
    const float* B = A + 1024;                                          // k
    float* Cp = g_sbuf + (size_t)z * LI_ * LI_;
    gemm_tn_body(A, 3072, B, 3072, Cp, LI_, DH_, nullptr, nullptr);
}

// Batched P @ V per (image, head): -> g_attout[q][h*64+d]
__global__ void k_pv()
{
    int z = blockIdx.z, img = z >> 4, h = z & 15;
    const float* A = g_sbuf + (size_t)z * LI_ * LI_;                    // probs
    const float* B = g_qkv + (size_t)img * LI_ * 3072 + 2048 + h * 64;  // v
    float* Cp = g_attout + (size_t)img * LI_ * DIM_ + h * 64;
    gemm_nn_body(A, LI_, B, 3072, Cp, DIM_, LI_);
}

// ======================================================================
// RoPE (in place on q,k parts of g_qkv). 512 threads: (h, d<32) pairs.
// ======================================================================
__global__ void k_rope(const float* __restrict__ rope)
{
    int s = blockIdx.x;
    int t = threadIdx.x;
    int h = t >> 5, d = t & 31;
    float ang = rope[(size_t)s * 32 + d];
    float c = cosf(ang), sn = sinf(ang);
    float* q = g_qkv + (size_t)s * 3072 + h * 64;
    float* k = q + 1024;
    float q1 = q[d], q2 = q[d + 32];
    q[d]      = q1 * c - q2 * sn;
    q[d + 32] = q2 * c + q1 * sn;
    float k1 = k[d], k2 = k[d + 32];
    k[d]      = k1 * c - k2 * sn;
    k[d + 32] = k2 * c + k1 * sn;
}

// ======================================================================
// Index scores: one block per global query row; 256 threads over 512 keys.
// ======================================================================
__global__ void k_idx_scores(const int* __restrict__ coords,
                             const float* __restrict__ W1g, const float* __restrict__ b1g,
                             const float* __restrict__ W2g, const float* __restrict__ b2g,
                             const float* __restrict__ rpe_table)
{
    int gq   = blockIdx.x;
    int img  = gq >> 9;
    int base = img << 9;
    __shared__ float qrow[128];
    __shared__ float w1s[GH_ * IH_], w2s[IH_ * GH_], b1s[GH_], b2s[IH_];
    __shared__ float rpes[NBUCK_ * IH_];
    __shared__ int   poss[LI_];
    int t = threadIdx.x;
    if (t < 128) qrow[t] = g_qI[(size_t)gq * 128 + t];
    if (t < 32) w1s[t] = W1g[t];
    else if (t < 64) w2s[t - 32] = W2g[t - 32];
    else if (t < 72) b1s[t - 64] = b1g[t - 64];
    else if (t < 76) b2s[t - 72] = b2g[t - 72];
    for (int i = t; i < NBUCK_ * IH_; i += 256) rpes[i] = rpe_table[i];
    for (int i = t; i < LI_; i += 256) poss[i] = coords[(size_t)(base + i) * 2 + 1];
    __syncthreads();
    int posq = coords[(size_t)gq * 2 + 1];
    float* out = g_scores + (size_t)img * LI_ * LI_ + (size_t)(gq & 511) * LI_;

    for (int k = t; k < LI_; k += 256) {
        const float* krow = g_kI + (size_t)(base + k) * 128;
        float dot[8];
        #pragma unroll
        for (int h = 0; h < 8; h++) {
            float s = 0.f;
            #pragma unroll
            for (int d4 = 0; d4 < 4; d4++) {
                float4 a = *(const float4*)&qrow[h * 16 + d4 * 4];
                float4 b = *(const float4*)&krow[h * 16 + d4 * 4];
                s += a.x*b.x + a.y*b.y + a.z*b.z + a.w*b.w;
            }
            dot[h] = s;
        }
        int rel = posq - poss[k];
        rel = rel < -64 ? -64 : (rel > 64 ? 64 : rel);
        const float* rp = &rpes[(rel + 64) * IH_];
        float xg[IH_];
        #pragma unroll
        for (int i = 0; i < IH_; i++) xg[i] = dot[IH_ + i] + rp[i];
        float hg[GH_];
        #pragma unroll
        for (int j = 0; j < GH_; j++) {
            float s = b1s[j];
            #pragma unroll
            for (int i = 0; i < IH_; i++) s = fmaf(w1s[j * IH_ + i], xg[i], s);
            hg[j] = fmaxf(s, 0.f);
        }
        float score = 0.f;
        #pragma unroll
        for (int i = 0; i < IH_; i++) {
            float s = b2s[i];
            #pragma unroll
            for (int j = 0; j < GH_; j++) s = fmaf(w2s[i * GH_ + j], hg[j], s);
            float gi = 1.f / (1.f + expf(-s));
            float rs = fmaxf(dot[i] + rp[i], 0.f);
            score = fmaf(rs, gi, score);
        }
        out[k] = score;
    }
}

// ======================================================================
// Exact top-K (K=256 of 512) per query row via 4-pass radix select on
// order-preserving float->uint keys. Ties at the K-th value are taken in
// ascending key-index order (matches jax.lax.top_k). Emits 512-bit mask.
// ======================================================================
__global__ void k_topk()
{
    int row  = blockIdx.x;           // global q = img*512 + q
    int img  = row >> 9;
    const float* sc = g_scores + (size_t)img * LI_ * LI_ + (size_t)(row & 511) * LI_;
    __shared__ unsigned skeys[LI_];
    __shared__ unsigned hist[256];
    __shared__ unsigned mwords[16];
    __shared__ unsigned short eqidx[LI_];
    __shared__ unsigned s_prefix, s_kth, s_eqcnt;
    int t = threadIdx.x;

    for (int i = t; i < LI_; i += 256) {
        unsigned u = __float_as_uint(sc[i]);
        u = (u & 0x80000000u) ? ~u : (u | 0x80000000u);
        skeys[i] = u;
    }
    if (t == 0) { s_prefix = 0; s_kth = KSEL_; s_eqcnt = 0; }
    if (t < 16) mwords[t] = 0;
    __syncthreads();

    unsigned prefmask = 0;
    for (int r = 0; r < 4; r++) {
        int shift = 24 - 8 * r;
        for (int i = t; i < 256; i += 256) hist[i] = 0;
        __syncthreads();
        unsigned pref = s_prefix;
        for (int i = t; i < LI_; i += 256) {
            unsigned u = skeys[i];
            if ((u & prefmask) == pref) atomicAdd(&hist[(u >> shift) & 255], 1u);
        }
        __syncthreads();
        if (t == 0) {
            unsigned kth = s_kth, cum = 0;
            int b = 255;
            for (; b >= 0; b--) { cum += hist[b]; if (cum >= kth) break; }
            s_kth    = kth - (cum - hist[b]);
            s_prefix = pref | ((unsigned)b << shift);
        }
        prefmask |= (0xFFu << shift);
        __syncthreads();
    }
    unsigned tau = s_prefix;   // exact K-th largest key

    for (int i = t; i < LI_; i += 256) {
        unsigned u = skeys[i];
        if (u > tau) {
            atomicOr(&mwords[i >> 5], 1u << (i & 31));
        } else if (u == tau) {
            unsigned p = atomicAdd(&s_eqcnt, 1u);
            eqidx[p] = (unsigned short)i;
        }
    }
    __syncthreads();
    if (t == 0) {
        int cg = 0;
        #pragma unroll
        for (int w = 0; w < 16; w++) cg += __popc(mwords[w]);
        int need = KSEL_ - cg;
        int ce = (int)s_eqcnt;
        if (need > 0) {
            if (ce <= need) {
                for (int j = 0; j < ce; j++) { int i = eqidx[j]; mwords[i >> 5] |= 1u << (i & 31); }
            } else {
                // take 'need' smallest indices among ties (insertion sort; ce is tiny in practice)
                for (int a = 1; a < ce; a++) {
                    unsigned short v = eqidx[a]; int b = a - 1;
                    while (b >= 0 && eqidx[b] > v) { eqidx[b + 1] = eqidx[b]; b--; }
                    eqidx[b + 1] = v;
                }
                for (int j = 0; j < need; j++) { int i = eqidx[j]; mwords[i >> 5] |= 1u << (i & 31); }
            }
        }
    }
    __syncthreads();
    if (t < 16) g_selmask[(size_t)row * 16 + t] = mwords[t];
}

// ======================================================================
// Masked softmax in place on g_sbuf rows. Row = (img*16+h)*512 + q.
// Applies 1/sqrt(DH)=0.125 scale; unselected keys -> prob 0.
// ======================================================================
__global__ void k_softmax()
{
    int r   = blockIdx.x;
    int q   = r & 511;
    int img = r >> 13;
    float* row = g_sbuf + (size_t)r * LI_;
    const unsigned* mw = g_selmask + ((size_t)((img << 9) + q)) * 16;
    int t = threadIdx.x;   // 256 threads, 2 elems each
    __shared__ float red[256];
    __shared__ unsigned mws[16];
    if (t < 16) mws[t] = mw[t];
    __syncthreads();

    float v[2];
    float mx = -1e30f;
    #pragma unroll
    for (int i = 0; i < 2; i++) {
        int k = t + i * 256;
        bool sel = (mws[k >> 5] >> (k & 31)) & 1u;
        v[i] = sel ? row[k] * 0.125f : -1e30f;
        mx = fmaxf(mx, v[i]);
    }
    red[t] = mx; __syncthreads();
    for (int s = 128; s > 0; s >>= 1) { if (t < s) red[t] = fmaxf(red[t], red[t + s]); __syncthreads(); }
    mx = red[0]; __syncthreads();

    float sm = 0.f;
    #pragma unroll
    for (int i = 0; i < 2; i++) {
        v[i] = (v[i] > -1e29f) ? expf(v[i] - mx) : 0.f;
        sm += v[i];
    }
    red[t] = sm; __syncthreads();
    for (int s = 128; s > 0; s >>= 1) { if (t < s) red[t] += red[t + s]; __syncthreads(); }
    float inv = 1.f / red[0];
    #pragma unroll
    for (int i = 0; i < 2; i++) row[t + i * 256] = v[i] * inv;
}

// ======================================================================
// Launch
// ======================================================================
extern "C" void kernel_launch(void* const* d_in, const int* in_sizes, int n_in,
                              void* d_out, int out_size)
{
    const float* hs     = (const float*)d_in[0];
    const int*   coords = (const int*)  d_in[1];
    // d_in[2] = cu_seqlens (layout fixed: 4 equal images of 512)
    const float* rope   = (const float*)d_in[3];
    const float* Wq_idx = (const float*)d_in[4];
    const float* Wk_idx = (const float*)d_in[5];
    const float* W1g    = (const float*)d_in[6];
    const float* b1g    = (const float*)d_in[7];
    const float* W2g    = (const float*)d_in[8];
    const float* b2g    = (const float*)d_in[9];
    const float* rpe    = (const float*)d_in[10];
    const float* Wqkv_d = (const float*)d_in[11];
    const float* bqkv_d = (const float*)d_in[12];
    const float* Wqkv_u = (const float*)d_in[13];
    const float* bqkv_u = (const float*)d_in[14];
    const float* Wp_d   = (const float*)d_in[15];
    const float* bp_d   = (const float*)d_in[16];
    const float* Wp_u   = (const float*)d_in[17];
    const float* bp_u   = (const float*)d_in[18];
    const float* scaler = (const float*)d_in[19];
    float* out = (float*)d_out;

    float *tmp1, *qkv, *qI, *kI, *attout, *tmp2;
    cudaGetSymbolAddress((void**)&tmp1,   g_tmp1);
    cudaGetSymbolAddress((void**)&qkv,    g_qkv);
    cudaGetSymbolAddress((void**)&qI,     g_qI);
    cudaGetSymbolAddress((void**)&kI,     g_kI);
    cudaGetSymbolAddress((void**)&attout, g_attout);
    cudaGetSymbolAddress((void**)&tmp2,   g_tmp2);

    dim3 blk(256);

    // qkv = (hs @ Wqkv_d.T + b) @ Wqkv_u.T + b
    k_gemm_tn<<<dim3(BOT_ / 64, S_ / 64), blk>>>(hs, DIM_, Wqkv_d, DIM_, tmp1, BOT_, DIM_, bqkv_d, nullptr);
    k_gemm_tn<<<dim3(3 * DIM_ / 64, S_ / 64), blk>>>(tmp1, BOT_, Wqkv_u, BOT_, qkv, 3 * DIM_, BOT_, bqkv_u, nullptr);

    // RoPE on q,k
    k_rope<<<S_, 512>>>(rope);

    // index projections
    k_gemm_tn<<<dim3(2, S_ / 64), blk>>>(hs, DIM_, Wq_idx, DIM_, qI, 128, DIM_, nullptr, nullptr);
    k_gemm_tn<<<dim3(2, S_ / 64), blk>>>(hs, DIM_, Wk_idx, DIM_, kI, 128, DIM_, nullptr, nullptr);

    // index scores + exact top-K mask
    k_idx_scores<<<S_, 256>>>(coords, W1g, b1g, W2g, b2g, rpe);
    k_topk<<<S_, 256>>>();

    // attention: dense QK^T per (image,head), masked softmax, PV
    k_qk<<<dim3(8, 8, NIMG_ * H_), blk>>>();
    k_softmax<<<NIMG_ * H_ * LI_, 256>>>();
    k_pv<<<dim3(1, 8, NIMG_ * H_), blk>>>();

    // final projection (+ scaler)
    k_gemm_tn<<<dim3(BOT_ / 64, S_ / 64), blk>>>(attout, DIM_, Wp_d, DIM_, tmp2, BOT_, DIM_, bp_d, nullptr);
    k_gemm_tn<<<dim3(DIM_ / 64, S_ / 64), blk>>>(tmp2, BOT_, Wp_u, BOT_, out, DIM_, BOT_, bp_u, scaler);
}

// round 3
// speedup vs baseline: 1.3714x; 1.3714x over previous
#include <cuda_runtime.h>
#include <math.h>
#include <stdint.h>

// ---------------- problem constants ----------------
#define S_    2048
#define NIMG_ 4
#define LI_   512
#define H_    16
#define DH_   64
#define DIM_  1024
#define BOT_  256
#define KSEL_ 256
#define IH_   4
#define ID_   16
#define GH_   8
#define NBUCK_ 129

// ---------------- scratch (device globals; no runtime alloc) ----------------
__device__ float    g_tmp1[S_ * BOT_];
__device__ float    g_qkv [S_ * 3 * DIM_];
__device__ float    g_vt  [NIMG_ * H_ * DH_ * LI_];
__device__ float    g_qI  [S_ * 128];
__device__ float    g_kI  [S_ * 128];
__device__ float    g_scores[NIMG_ * LI_ * LI_];
__device__ unsigned g_selmask[S_ * 16];
__device__ float    g_sbuf[(size_t)NIMG_ * H_ * LI_ * LI_];
__device__ float    g_attout[S_ * DIM_];
__device__ float    g_tmp2[S_ * BOT_];

// ---------------- helpers ----------------
__device__ __forceinline__ uint32_t smem_u32(const void* p) {
    uint32_t a;
    asm("{ .reg .u64 t; cvta.to.shared.u64 t, %1; cvt.u32.u64 %0, t; }" : "=r"(a) : "l"(p));
    return a;
}
__device__ __forceinline__ void cp_async16(uint32_t sa, const void* gp) {
    asm volatile("cp.async.cg.shared.global [%0], [%1], 16;" :: "r"(sa), "l"(gp) : "memory");
}
__device__ __forceinline__ uint32_t f2tf32(float v) {
    uint32_t u;
    asm("cvt.rna.tf32.f32 %0, %1;" : "=r"(u) : "f"(v));
    return u;
}
__device__ __forceinline__ void mma8(float* c, const uint32_t* a, const uint32_t* b) {
    asm volatile("mma.sync.aligned.m16n8k8.row.col.f32.tf32.tf32.f32 "
        "{%0,%1,%2,%3}, {%4,%5,%6,%7}, {%8,%9}, {%0,%1,%2,%3};"
        : "+f"(c[0]), "+f"(c[1]), "+f"(c[2]), "+f"(c[3])
        : "r"(a[0]), "r"(a[1]), "r"(a[2]), "r"(a[3]), "r"(b[0]), "r"(b[1]));
}

// ======================================================================
// tf32 mma.sync GEMM (TN): C[m][n] = sum_k A[m,k]*B[n,k]  (+bias)*scaler
// 128 x NT block tile, 256 threads (8 warps, grid GM x GN), K-chunks of
// 32 with cp.async double buffering. Batched over blockIdx.z with affine
// (z/zdiv, z%zdiv) strides. Requires M%128==0, N%NT==0, K%32==0.
// ======================================================================
#define AST 36  // smem row stride in floats (32 data + 4 pad)

template<int NT>
__device__ __forceinline__ void load_chunk(
    const float* __restrict__ A, const float* __restrict__ B,
    int lda, int ldb, int m0, int n0, int k0,
    float* __restrict__ Abuf, float* __restrict__ Bbuf, int t)
{
    const int arow = t >> 3, ac4 = (t & 7) << 2;
    #pragma unroll
    for (int i = 0; i < 4; i++) {
        int row = arow + i * 32;
        cp_async16(smem_u32(Abuf + row * AST + ac4),
                   A + (long long)(m0 + row) * lda + k0 + ac4);
    }
    #pragma unroll
    for (int i = 0; i < NT / 32; i++) {
        int row = arow + i * 32;
        cp_async16(smem_u32(Bbuf + row * AST + ac4),
                   B + (long long)(n0 + row) * ldb + k0 + ac4);
    }
    asm volatile("cp.async.commit_group;" ::: "memory");
}

template<int MI, int NI>
__device__ __forceinline__ void compute_chunk(
    const float* __restrict__ Abuf, const float* __restrict__ Bbuf,
    int wm0, int wn0, int g, int l4, float (*acc)[4])
{
    #pragma unroll
    for (int ks = 0; ks < 4; ks++) {
        const int kk = ks * 8;
        uint32_t af[MI][4], bf[NI][2];
        #pragma unroll
        for (int mi = 0; mi < MI; mi++) {
            const float* p = Abuf + (wm0 + mi * 16 + g) * AST + kk + l4;
            af[mi][0] = f2tf32(p[0]);
            af[mi][2] = f2tf32(p[4]);
            af[mi][1] = f2tf32(p[8 * AST]);
            af[mi][3] = f2tf32(p[8 * AST + 4]);
        }
        #pragma unroll
        for (int ni = 0; ni < NI; ni++) {
            const float* p = Bbuf + (wn0 + ni * 8 + g) * AST + kk + l4;
            bf[ni][0] = f2tf32(p[0]);
            bf[ni][1] = f2tf32(p[4]);
        }
        #pragma unroll
        for (int mi = 0; mi < MI; mi++)
            #pragma unroll
            for (int ni = 0; ni < NI; ni++)
                mma8(acc[mi * NI + ni], af[mi], bf[ni]);
    }
}

template <int NT, int GM, int GN>
__global__ void __launch_bounds__(256, 1) k_mma_gemm(
    const float* __restrict__ A, int lda, long long sAhi, long long sAlo,
    const float* __restrict__ B, int ldb, long long sBhi, long long sBlo,
    float* __restrict__ C, int ldc, long long sChi, long long sClo,
    int K, int zdiv,
    const float* __restrict__ bias, const float* __restrict__ scaler)
{
    constexpr int WM = 128 / GM, WN = NT / GN;
    constexpr int MI = WM / 16, NI = WN / 8;
    extern __shared__ float sm[];
    float* Abuf[2] = { sm, sm + 128 * AST };
    float* Bbuf[2] = { sm + 2 * 128 * AST, sm + 2 * 128 * AST + NT * AST };

    const int z = blockIdx.z;
    A += (long long)(z / zdiv) * sAhi + (long long)(z % zdiv) * sAlo;
    B += (long long)(z / zdiv) * sBhi + (long long)(z % zdiv) * sBlo;
    C += (long long)(z / zdiv) * sChi + (long long)(z % zdiv) * sClo;

    const int m0 = blockIdx.y * 128, n0 = blockIdx.x * NT;
    const int t = threadIdx.x, wid = t >> 5, lane = t & 31;
    const int wm0 = (wid % GM) * WM, wn0 = (wid / GM) * WN;
    const int g = lane >> 2, l4 = lane & 3;

    float acc[MI * NI][4];
    #pragma unroll
    for (int i = 0; i < MI * NI; i++)
        #pragma unroll
        for (int r = 0; r < 4; r++) acc[i][r] = 0.f;

    const int nch = K >> 5;

    load_chunk<NT>(A, B, lda, ldb, m0, n0, 0, Abuf[0], Bbuf[0], t);
    asm volatile("cp.async.wait_group 0;" ::: "memory");
    __syncthreads();

    for (int ch = 0; ch < nch; ch++) {
        const int cur = ch & 1;
        if (ch + 1 < nch)
            load_chunk<NT>(A, B, lda, ldb, m0, n0, (ch + 1) << 5, Abuf[cur ^ 1], Bbuf[cur ^ 1], t);
        compute_chunk<MI, NI>(Abuf[cur], Bbuf[cur], wm0, wn0, g, l4, acc);
        if (ch + 1 < nch) {
            asm volatile("cp.async.wait_group 0;" ::: "memory");
            __syncthreads();
        }
    }

    // epilogue
    const float sc = scaler ? *scaler : 1.f;
    #pragma unroll
    for (int mi = 0; mi < MI; mi++) {
        const int r0 = m0 + wm0 + mi * 16 + g;
        #pragma unroll
        for (int ni = 0; ni < NI; ni++) {
            const int col = n0 + wn0 + ni * 8 + 2 * l4;
            float bx = 0.f, by = 0.f;
            if (bias) { bx = bias[col]; by = bias[col + 1]; }
            const float* a = acc[mi * NI + ni];
            float2 v0 = { (a[0] + bx) * sc, (a[1] + by) * sc };
            float2 v1 = { (a[2] + bx) * sc, (a[3] + by) * sc };
            *(float2*)&C[(long long)r0 * ldc + col] = v0;
            *(float2*)&C[(long long)(r0 + 8) * ldc + col] = v1;
        }
    }
}

// ======================================================================
// fp32 SIMT GEMM (TN) — used ONLY for the index projections, where the
// downstream hard top-K selection cannot tolerate tf32 noise.
// ======================================================================
#define SMS 68
__global__ void k_gemm_tn(const float* __restrict__ A, int lda,
                          const float* __restrict__ B, int ldb,
                          float* __restrict__ C, int ldc, int K)
{
    __shared__ float As[16 * SMS];
    __shared__ float Bs[16 * SMS];
    const int t  = threadIdx.x;
    const int tx = t & 15, ty = t >> 4;
    const int m0 = blockIdx.y * 64, n0 = blockIdx.x * 64;
    const int lm = t >> 2;
    const int lk = (t & 3) << 2;
    const float* Ap = A + (size_t)(m0 + lm) * lda + lk;
    const float* Bp = B + (size_t)(n0 + lm) * ldb + lk;
    float acc[4][4] = {};
    for (int k0 = 0; k0 < K; k0 += 16) {
        float4 av = *(const float4*)(Ap + k0);
        float4 bv = *(const float4*)(Bp + k0);
        __syncthreads();
        As[(lk+0)*SMS+lm]=av.x; As[(lk+1)*SMS+lm]=av.y;
        As[(lk+2)*SMS+lm]=av.z; As[(lk+3)*SMS+lm]=av.w;
        Bs[(lk+0)*SMS+lm]=bv.x; Bs[(lk+1)*SMS+lm]=bv.y;
        Bs[(lk+2)*SMS+lm]=bv.z; Bs[(lk+3)*SMS+lm]=bv.w;
        __syncthreads();
        #pragma unroll
        for (int kk = 0; kk < 16; kk++) {
            float4 a = *(const float4*)&As[kk*SMS + (ty<<2)];
            float4 b = *(const float4*)&Bs[kk*SMS + (tx<<2)];
            float ar[4] = {a.x,a.y,a.z,a.w};
            float br[4] = {b.x,b.y,b.z,b.w};
            #pragma unroll
            for (int i=0;i<4;i++)
                #pragma unroll
                for (int j=0;j<4;j++)
                    acc[i][j] = fmaf(ar[i], br[j], acc[i][j]);
        }
    }
    #pragma unroll
    for (int i=0;i<4;i++){
        int m = m0 + (ty<<2) + i;
        #pragma unroll
        for (int j=0;j<4;j++)
            C[(size_t)m*ldc + n0 + (tx<<2) + j] = acc[i][j];
    }
}

// ======================================================================
// V transpose: g_vt[z][d][k] = V[img][k][h*64+d]   (z = img*16+h)
// ======================================================================
__global__ void k_vt()
{
    __shared__ float s[32][65];
    const int z = blockIdx.x, kb = blockIdx.y;
    const int img = z >> 4, h = z & 15;
    const int t = threadIdx.x;
    const float* V = g_qkv + (size_t)img * LI_ * 3072 + 2048 + h * 64;
    const int kk = t >> 6, d = t & 63;
    #pragma unroll
    for (int i = 0; i < 8; i++) {
        int k = kb * 32 + kk + i * 4;
        s[kk + i * 4][d] = V[(size_t)k * 3072 + d];
    }
    __syncthreads();
    float* out = g_vt + (size_t)z * (DH_ * LI_) + kb * 32;
    const int ko = t & 31, dw = t >> 5;
    #pragma unroll
    for (int i = 0; i < 8; i++) {
        int dd = dw + i * 8;
        out[(size_t)dd * LI_ + ko] = s[ko][dd];
    }
}

// ======================================================================
// RoPE (in place on q,k parts of g_qkv).
// ======================================================================
__global__ void k_rope(const float* __restrict__ rope)
{
    int s = blockIdx.x;
    int t = threadIdx.x;
    int h = t >> 5, d = t & 31;
    float ang = rope[(size_t)s * 32 + d];
    float c = cosf(ang), sn = sinf(ang);
    float* q = g_qkv + (size_t)s * 3072 + h * 64;
    float* k = q + 1024;
    float q1 = q[d], q2 = q[d + 32];
    q[d]      = q1 * c - q2 * sn;
    q[d + 32] = q2 * c + q1 * sn;
    float k1 = k[d], k2 = k[d + 32];
    k[d]      = k1 * c - k2 * sn;
    k[d + 32] = k2 * c + k1 * sn;
}

// ======================================================================
// Index scores
// ======================================================================
__global__ void k_idx_scores(const int* __restrict__ coords,
                             const float* __restrict__ W1g, const float* __restrict__ b1g,
                             const float* __restrict__ W2g, const float* __restrict__ b2g,
                             const float* __restrict__ rpe_table)
{
    int gq   = blockIdx.x;
    int img  = gq >> 9;
    int base = img << 9;
    __shared__ float qrow[128];
    __shared__ float w1s[GH_ * IH_], w2s[IH_ * GH_], b1s[GH_], b2s[IH_];
    __shared__ float rpes[NBUCK_ * IH_];
    __shared__ int   poss[LI_];
    int t = threadIdx.x;
    if (t < 128) qrow[t] = g_qI[(size_t)gq * 128 + t];
    if (t < 32) w1s[t] = W1g[t];
    else if (t < 64) w2s[t - 32] = W2g[t - 32];
    else if (t < 72) b1s[t - 64] = b1g[t - 64];
    else if (t < 76) b2s[t - 72] = b2g[t - 72];
    for (int i = t; i < NBUCK_ * IH_; i += 256) rpes[i] = rpe_table[i];
    for (int i = t; i < LI_; i += 256) poss[i] = coords[(size_t)(base + i) * 2 + 1];
    __syncthreads();
    int posq = coords[(size_t)gq * 2 + 1];
    float* out = g_scores + (size_t)img * LI_ * LI_ + (size_t)(gq & 511) * LI_;

    for (int k = t; k < LI_; k += 256) {
        const float* krow = g_kI + (size_t)(base + k) * 128;
        float dot[8];
        #pragma unroll
        for (int h = 0; h < 8; h++) {
            float s = 0.f;
            #pragma unroll
            for (int d4 = 0; d4 < 4; d4++) {
                float4 a = *(const float4*)&qrow[h * 16 + d4 * 4];
                float4 b = *(const float4*)&krow[h * 16 + d4 * 4];
                s += a.x*b.x + a.y*b.y + a.z*b.z + a.w*b.w;
            }
            dot[h] = s;
        }
        int rel = posq - poss[k];
        rel = rel < -64 ? -64 : (rel > 64 ? 64 : rel);
        const float* rp = &rpes[(rel + 64) * IH_];
        float xg[IH_];
        #pragma unroll
        for (int i = 0; i < IH_; i++) xg[i] = dot[IH_ + i] + rp[i];
        float hg[GH_];
        #pragma unroll
        for (int j = 0; j < GH_; j++) {
            float s = b1s[j];
            #pragma unroll
            for (int i = 0; i < IH_; i++) s = fmaf(w1s[j * IH_ + i], xg[i], s);
            hg[j] = fmaxf(s, 0.f);
        }
        float score = 0.f;
        #pragma unroll
        for (int i = 0; i < IH_; i++) {
            float s = b2s[i];
            #pragma unroll
            for (int j = 0; j < GH_; j++) s = fmaf(w2s[i * GH_ + j], hg[j], s);
            float gi = 1.f / (1.f + expf(-s));
            float rs = fmaxf(dot[i] + rp[i], 0.f);
            score = fmaf(rs, gi, score);
        }
        out[k] = score;
    }
}

// ======================================================================
// Exact top-K (K=256 of 512) per query row via 4-pass radix select.
// ======================================================================
__global__ void k_topk()
{
    int row  = blockIdx.x;
    int img  = row >> 9;
    const float* sc = g_scores + (size_t)img * LI_ * LI_ + (size_t)(row & 511) * LI_;
    __shared__ unsigned skeys[LI_];
    __shared__ unsigned hist[256];
    __shared__ unsigned mwords[16];
    __shared__ unsigned short eqidx[LI_];
    __shared__ unsigned s_prefix, s_kth, s_eqcnt;
    int t = threadIdx.x;

    for (int i = t; i < LI_; i += 256) {
        unsigned u = __float_as_uint(sc[i]);
        u = (u & 0x80000000u) ? ~u : (u | 0x80000000u);
        skeys[i] = u;
    }
    if (t == 0) { s_prefix = 0; s_kth = KSEL_; s_eqcnt = 0; }
    if (t < 16) mwords[t] = 0;
    __syncthreads();

    unsigned prefmask = 0;
    for (int r = 0; r < 4; r++) {
        int shift = 24 - 8 * r;
        for (int i = t; i < 256; i += 256) hist[i] = 0;
        __syncthreads();
        unsigned pref = s_prefix;
        for (int i = t; i < LI_; i += 256) {
            unsigned u = skeys[i];
            if ((u & prefmask) == pref) atomicAdd(&hist[(u >> shift) & 255], 1u);
        }
        __syncthreads();
        if (t == 0) {
            unsigned kth = s_kth, cum = 0;
            int b = 255;
            for (; b >= 0; b--) { cum += hist[b]; if (cum >= kth) break; }
            s_kth    = kth - (cum - hist[b]);
            s_prefix = pref | ((unsigned)b << shift);
        }
        prefmask |= (0xFFu << shift);
        __syncthreads();
    }
    unsigned tau = s_prefix;

    for (int i = t; i < LI_; i += 256) {
        unsigned u = skeys[i];
        if (u > tau) {
            atomicOr(&mwords[i >> 5], 1u << (i & 31));
        } else if (u == tau) {
            unsigned p = atomicAdd(&s_eqcnt, 1u);
            eqidx[p] = (unsigned short)i;
        }
    }
    __syncthreads();
    if (t == 0) {
        int cg = 0;
        #pragma unroll
        for (int w = 0; w < 16; w++) cg += __popc(mwords[w]);
        int need = KSEL_ - cg;
        int ce = (int)s_eqcnt;
        if (need > 0) {
            if (ce <= need) {
                for (int j = 0; j < ce; j++) { int i = eqidx[j]; mwords[i >> 5] |= 1u << (i & 31); }
            } else {
                for (int a = 1; a < ce; a++) {
                    unsigned short v = eqidx[a]; int b = a - 1;
                    while (b >= 0 && eqidx[b] > v) { eqidx[b + 1] = eqidx[b]; b--; }
                    eqidx[b + 1] = v;
                }
                for (int j = 0; j < need; j++) { int i = eqidx[j]; mwords[i >> 5] |= 1u << (i & 31); }
            }
        }
    }
    __syncthreads();
    if (t < 16) g_selmask[(size_t)row * 16 + t] = mwords[t];
}

// ======================================================================
// Masked softmax in place on g_sbuf rows. Row = (img*16+h)*512 + q.
// ======================================================================
__global__ void k_softmax()
{
    int r   = blockIdx.x;
    int q   = r & 511;
    int img = r >> 13;
    float* row = g_sbuf + (size_t)r * LI_;
    const unsigned* mw = g_selmask + ((size_t)((img << 9) + q)) * 16;
    int t = threadIdx.x;
    __shared__ float red[256];
    __shared__ unsigned mws[16];
    if (t < 16) mws[t] = mw[t];
    __syncthreads();

    float v[2];
    float mx = -1e30f;
    #pragma unroll
    for (int i = 0; i < 2; i++) {
        int k = t + i * 256;
        bool sel = (mws[k >> 5] >> (k & 31)) & 1u;
        v[i] = sel ? row[k] * 0.125f : -1e30f;
        mx = fmaxf(mx, v[i]);
    }
    red[t] = mx; __syncthreads();
    for (int s = 128; s > 0; s >>= 1) { if (t < s) red[t] = fmaxf(red[t], red[t + s]); __syncthreads(); }
    mx = red[0]; __syncthreads();

    float sm = 0.f;
    #pragma unroll
    for (int i = 0; i < 2; i++) {
        v[i] = (v[i] > -1e29f) ? expf(v[i] - mx) : 0.f;
        sm += v[i];
    }
    red[t] = sm; __syncthreads();
    for (int s = 128; s > 0; s >>= 1) { if (t < s) red[t] += red[t + s]; __syncthreads(); }
    float inv = 1.f / red[0];
    #pragma unroll
    for (int i = 0; i < 2; i++) row[t + i * 256] = v[i] * inv;
}

// ======================================================================
// Launch
// ======================================================================
extern "C" void kernel_launch(void* const* d_in, const int* in_sizes, int n_in,
                              void* d_out, int out_size)
{
    const float* hs     = (const float*)d_in[0];
    const int*   coords = (const int*)  d_in[1];
    const float* rope   = (const float*)d_in[3];
    const float* Wq_idx = (const float*)d_in[4];
    const float* Wk_idx = (const float*)d_in[5];
    const float* W1g    = (const float*)d_in[6];
    const float* b1g    = (const float*)d_in[7];
    const float* W2g    = (const float*)d_in[8];
    const float* b2g    = (const float*)d_in[9];
    const float* rpe    = (const float*)d_in[10];
    const float* Wqkv_d = (const float*)d_in[11];
    const float* bqkv_d = (const float*)d_in[12];
    const float* Wqkv_u = (const float*)d_in[13];
    const float* bqkv_u = (const float*)d_in[14];
    const float* Wp_d   = (const float*)d_in[15];
    const float* bp_d   = (const float*)d_in[16];
    const float* Wp_u   = (const float*)d_in[17];
    const float* bp_u   = (const float*)d_in[18];
    const float* scaler = (const float*)d_in[19];
    float* out = (float*)d_out;

    float *tmp1, *qkv, *vt, *qI, *kI, *sbuf, *attout, *tmp2;
    cudaGetSymbolAddress((void**)&tmp1,   g_tmp1);
    cudaGetSymbolAddress((void**)&qkv,    g_qkv);
    cudaGetSymbolAddress((void**)&vt,     g_vt);
    cudaGetSymbolAddress((void**)&qI,     g_qI);
    cudaGetSymbolAddress((void**)&kI,     g_kI);
    cudaGetSymbolAddress((void**)&sbuf,   g_sbuf);
    cudaGetSymbolAddress((void**)&attout, g_attout);
    cudaGetSymbolAddress((void**)&tmp2,   g_tmp2);

    const int dyn128 = (2 * 128 + 2 * 128) * AST * 4;  // 73728
    const int dyn64  = (2 * 128 + 2 * 64)  * AST * 4;  // 55296
    cudaFuncSetAttribute((const void*)k_mma_gemm<128,2,4>, cudaFuncAttributeMaxDynamicSharedMemorySize, dyn128);
    cudaFuncSetAttribute((const void*)k_mma_gemm<64,4,2>,  cudaFuncAttributeMaxDynamicSharedMemorySize, dyn64);

    // qkv = (hs @ Wqkv_d.T + b) @ Wqkv_u.T + b
    k_mma_gemm<64,4,2><<<dim3(4, 16, 1), 256, dyn64>>>(
        hs, DIM_, 0, 0, Wqkv_d, DIM_, 0, 0, tmp1, BOT_, 0, 0, DIM_, 1, bqkv_d, nullptr);
    k_mma_gemm<128,2,4><<<dim3(24, 16, 1), 256, dyn128>>>(
        tmp1, BOT_, 0, 0, Wqkv_u, BOT_, 0, 0, qkv, 3 * DIM_, 0, 0, BOT_, 1, bqkv_u, nullptr);

    // V^T (rope only touches q,k, so order is free)
    k_vt<<<dim3(NIMG_ * H_, 16), 256>>>();
    k_rope<<<S_, 512>>>(rope);

    // index projections (fp32 SIMT — selection must be noise-free)
    k_gemm_tn<<<dim3(2, 32), 256>>>(hs, DIM_, Wq_idx, DIM_, qI, 128, DIM_);
    k_gemm_tn<<<dim3(2, 32), 256>>>(hs, DIM_, Wk_idx, DIM_, kI, 128, DIM_);

    // index scores + exact top-K mask
    k_idx_scores<<<S_, 256>>>(coords, W1g, b1g, W2g, b2g, rpe);
    k_topk<<<S_, 256>>>();

    // attention: QK^T (batched over img*16+h), masked softmax, P@V
    k_mma_gemm<128,2,4><<<dim3(4, 4, 64), 256, dyn128>>>(
        qkv, 3072, (long long)LI_ * 3072, 64,
        qkv + 1024, 3072, (long long)LI_ * 3072, 64,
        sbuf, LI_, (long long)16 * LI_ * LI_, (long long)LI_ * LI_,
        DH_, 16, nullptr, nullptr);
    k_softmax<<<NIMG_ * H_ * LI_, 256>>>();
    k_mma_gemm<64,4,2><<<dim3(1, 4, 64), 256, dyn64>>>(
        sbuf, LI_, (long long)16 * LI_ * LI_, (long long)LI_ * LI_,
        vt, LI_, (long long)16 * DH_ * LI_, (long long)DH_ * LI_,
        attout, DIM_, (long long)LI_ * DIM_, 64,
        LI_, 16, nullptr, nullptr);

    // final projection (+ scaler)
    k_mma_gemm<64,4,2><<<dim3(4, 16, 1), 256, dyn64>>>(
        attout, DIM_, 0, 0, Wp_d, DIM_, 0, 0, tmp2, BOT_, 0, 0, DIM_, 1, bp_d, nullptr);
    k_mma_gemm<128,2,4><<<dim3(8, 16, 1), 256, dyn128>>>(
        tmp2, BOT_, 0, 0, Wp_u, BOT_, 0, 0, out, DIM_, 0, 0, BOT_, 1, bp_u, scaler);
}

// round 4
// speedup vs baseline: 1.9826x; 1.4456x over previous
#include <cuda_runtime.h>
#include <math.h>
#include <stdint.h>

// ---------------- problem constants ----------------
#define S_    2048
#define NIMG_ 4
#define LI_   512
#define H_    16
#define DH_   64
#define DIM_  1024
#define BOT_  256
#define KSEL_ 256
#define IH_   4
#define ID_   16
#define GH_   8
#define NBUCK_ 129
#define FNEG  -1e30f

// ---------------- scratch (device globals; no runtime alloc) ----------------
__device__ float    g_tmp1[S_ * BOT_];
__device__ float    g_qkv [S_ * 3 * DIM_];
__device__ float    g_vt  [NIMG_ * H_ * DH_ * LI_];
__device__ float    g_qI  [S_ * 128];
__device__ float    g_kI  [S_ * 128];
__device__ float    g_scores[NIMG_ * LI_ * LI_];
__device__ unsigned g_selmask[S_ * 16];
__device__ float    g_attout[S_ * DIM_];
__device__ float    g_tmp2[S_ * BOT_];

// ---------------- helpers ----------------
__device__ __forceinline__ uint32_t smem_u32(const void* p) {
    uint32_t a;
    asm("{ .reg .u64 t; cvta.to.shared.u64 t, %1; cvt.u32.u64 %0, t; }" : "=r"(a) : "l"(p));
    return a;
}
__device__ __forceinline__ void cp_async16(uint32_t sa, const void* gp) {
    asm volatile("cp.async.cg.shared.global [%0], [%1], 16;" :: "r"(sa), "l"(gp) : "memory");
}
__device__ __forceinline__ uint32_t f2tf32(float v) {
    uint32_t u;
    asm("cvt.rna.tf32.f32 %0, %1;" : "=r"(u) : "f"(v));
    return u;
}
__device__ __forceinline__ void mma8(float* c, const uint32_t* a, const uint32_t* b) {
    asm volatile("mma.sync.aligned.m16n8k8.row.col.f32.tf32.tf32.f32 "
        "{%0,%1,%2,%3}, {%4,%5,%6,%7}, {%8,%9}, {%0,%1,%2,%3};"
        : "+f"(c[0]), "+f"(c[1]), "+f"(c[2]), "+f"(c[3])
        : "r"(a[0]), "r"(a[1]), "r"(a[2]), "r"(a[3]), "r"(b[0]), "r"(b[1]));
}

// ======================================================================
// tf32 mma.sync GEMM (TN): C[m][n] = sum_k A[m,k]*B[n,k]  (+bias)*scaler
// ======================================================================
#define AST 36

template<int NT>
__device__ __forceinline__ void load_chunk(
    const float* __restrict__ A, const float* __restrict__ B,
    int lda, int ldb, int m0, int n0, int k0,
    float* __restrict__ Abuf, float* __restrict__ Bbuf, int t)
{
    const int arow = t >> 3, ac4 = (t & 7) << 2;
    #pragma unroll
    for (int i = 0; i < 4; i++) {
        int row = arow + i * 32;
        cp_async16(smem_u32(Abuf + row * AST + ac4),
                   A + (long long)(m0 + row) * lda + k0 + ac4);
    }
    #pragma unroll
    for (int i = 0; i < NT / 32; i++) {
        int row = arow + i * 32;
        cp_async16(smem_u32(Bbuf + row * AST + ac4),
                   B + (long long)(n0 + row) * ldb + k0 + ac4);
    }
    asm volatile("cp.async.commit_group;" ::: "memory");
}

template<int MI, int NI>
__device__ __forceinline__ void compute_chunk(
    const float* __restrict__ Abuf, const float* __restrict__ Bbuf,
    int wm0, int wn0, int g, int l4, float (*acc)[4])
{
    #pragma unroll
    for (int ks = 0; ks < 4; ks++) {
        const int kk = ks * 8;
        uint32_t af[MI][4], bf[NI][2];
        #pragma unroll
        for (int mi = 0; mi < MI; mi++) {
            const float* p = Abuf + (wm0 + mi * 16 + g) * AST + kk + l4;
            af[mi][0] = f2tf32(p[0]);
            af[mi][2] = f2tf32(p[4]);
            af[mi][1] = f2tf32(p[8 * AST]);
            af[mi][3] = f2tf32(p[8 * AST + 4]);
        }
        #pragma unroll
        for (int ni = 0; ni < NI; ni++) {
            const float* p = Bbuf + (wn0 + ni * 8 + g) * AST + kk + l4;
            bf[ni][0] = f2tf32(p[0]);
            bf[ni][1] = f2tf32(p[4]);
        }
        #pragma unroll
        for (int mi = 0; mi < MI; mi++)
            #pragma unroll
            for (int ni = 0; ni < NI; ni++)
                mma8(acc[mi * NI + ni], af[mi], bf[ni]);
    }
}

template <int NT, int GM, int GN>
__global__ void __launch_bounds__(256, 1) k_mma_gemm(
    const float* __restrict__ A, int lda,
    const float* __restrict__ B, int ldb,
    float* __restrict__ C, int ldc, int K,
    const float* __restrict__ bias, const float* __restrict__ scaler)
{
    constexpr int WM = 128 / GM, WN = NT / GN;
    constexpr int MI = WM / 16, NI = WN / 8;
    extern __shared__ float sm[];
    float* Abuf[2] = { sm, sm + 128 * AST };
    float* Bbuf[2] = { sm + 2 * 128 * AST, sm + 2 * 128 * AST + NT * AST };

    const int m0 = blockIdx.y * 128, n0 = blockIdx.x * NT;
    const int t = threadIdx.x, wid = t >> 5, lane = t & 31;
    const int wm0 = (wid % GM) * WM, wn0 = (wid / GM) * WN;
    const int g = lane >> 2, l4 = lane & 3;

    float acc[MI * NI][4];
    #pragma unroll
    for (int i = 0; i < MI * NI; i++)
        #pragma unroll
        for (int r = 0; r < 4; r++) acc[i][r] = 0.f;

    const int nch = K >> 5;
    load_chunk<NT>(A, B, lda, ldb, m0, n0, 0, Abuf[0], Bbuf[0], t);
    asm volatile("cp.async.wait_group 0;" ::: "memory");
    __syncthreads();

    for (int ch = 0; ch < nch; ch++) {
        const int cur = ch & 1;
        if (ch + 1 < nch)
            load_chunk<NT>(A, B, lda, ldb, m0, n0, (ch + 1) << 5, Abuf[cur ^ 1], Bbuf[cur ^ 1], t);
        compute_chunk<MI, NI>(Abuf[cur], Bbuf[cur], wm0, wn0, g, l4, acc);
        if (ch + 1 < nch) {
            asm volatile("cp.async.wait_group 0;" ::: "memory");
            __syncthreads();
        }
    }

    const float sc = scaler ? *scaler : 1.f;
    #pragma unroll
    for (int mi = 0; mi < MI; mi++) {
        const int r0 = m0 + wm0 + mi * 16 + g;
        #pragma unroll
        for (int ni = 0; ni < NI; ni++) {
            const int col = n0 + wn0 + ni * 8 + 2 * l4;
            float bx = 0.f, by = 0.f;
            if (bias) { bx = bias[col]; by = bias[col + 1]; }
            const float* a = acc[mi * NI + ni];
            float2 v0 = { (a[0] + bx) * sc, (a[1] + by) * sc };
            float2 v1 = { (a[2] + bx) * sc, (a[3] + by) * sc };
            *(float2*)&C[(long long)r0 * ldc + col] = v0;
            *(float2*)&C[(long long)(r0 + 8) * ldc + col] = v1;
        }
    }
}

// ======================================================================
// Fused flash attention: per block (img*16+h, q-tile of 128):
// S = Q@K^T (tf32 mma) -> mask+scale -> online softmax -> O += P@V.
// ======================================================================
__global__ void __launch_bounds__(256, 1) k_flash()
{
    extern __shared__ float sm[];
    float* Qs  = sm;                 // [128][68]
    float* Ks  = Qs + 128 * 68;      // [128][68]
    float* VTs = Ks + 128 * 68;      // [64][132]
    float* Ps  = VTs + 64 * 132;     // [128][132]
    unsigned* mskS = (unsigned*)(Ps + 128 * 132);  // [128][16]

    const int qt = blockIdx.x, z = blockIdx.y;
    const int img = z >> 4, h = z & 15;
    const int t = threadIdx.x, w = t >> 5, lane = t & 31;
    const int g = lane >> 2, l4 = lane & 3;
    const int qrow0 = img * 512 + qt * 128;

    const float* Qg  = g_qkv + (size_t)qrow0 * 3072 + h * 64;
    const float* Kg0 = g_qkv + (size_t)img * 512 * 3072 + 1024 + h * 64;
    const float* VTg = g_vt + (size_t)z * (DH_ * LI_);

    // load Q tile + mask words
    #pragma unroll
    for (int i = 0; i < 8; i++) {
        int fid = t + i * 256;
        int row = fid >> 4, c4 = (fid & 15) << 2;
        cp_async16(smem_u32(Qs + row * 68 + c4), Qg + (size_t)row * 3072 + c4);
    }
    asm volatile("cp.async.commit_group;" ::: "memory");
    #pragma unroll
    for (int i = 0; i < 8; i++) {
        int widx = t + i * 256;
        mskS[widx] = g_selmask[(size_t)qrow0 * 16 + widx];
    }
    asm volatile("cp.async.wait_group 0;" ::: "memory");
    __syncthreads();

    // Q fragments (warp owns rows w*16 .. w*16+15)
    const int rA = w * 16 + g, rB = rA + 8;
    uint32_t qf[8][4];
    #pragma unroll
    for (int kk = 0; kk < 8; kk++) {
        const float* p = Qs + kk * 8 + l4;
        qf[kk][0] = f2tf32(p[rA * 68]);
        qf[kk][1] = f2tf32(p[rB * 68]);
        qf[kk][2] = f2tf32(p[rA * 68 + 4]);
        qf[kk][3] = f2tf32(p[rB * 68 + 4]);
    }

    float mrow0 = FNEG, mrow1 = FNEG, lrow0 = 0.f, lrow1 = 0.f;
    float oacc[8][4];
    #pragma unroll
    for (int i = 0; i < 8; i++)
        #pragma unroll
        for (int r = 0; r < 4; r++) oacc[i][r] = 0.f;

    for (int kt = 0; kt < 4; kt++) {
        // K tile (group A), VT tile (group B)
        const float* Kg = Kg0 + (size_t)(kt * 128) * 3072;
        #pragma unroll
        for (int i = 0; i < 8; i++) {
            int fid = t + i * 256;
            int row = fid >> 4, c4 = (fid & 15) << 2;
            cp_async16(smem_u32(Ks + row * 68 + c4), Kg + (size_t)row * 3072 + c4);
        }
        asm volatile("cp.async.commit_group;" ::: "memory");
        #pragma unroll
        for (int i = 0; i < 8; i++) {
            int fid = t + i * 256;
            int row = fid >> 5, c4 = (fid & 31) << 2;
            cp_async16(smem_u32(VTs + row * 132 + c4), VTg + (size_t)row * 512 + kt * 128 + c4);
        }
        asm volatile("cp.async.commit_group;" ::: "memory");
        asm volatile("cp.async.wait_group 1;" ::: "memory");  // K ready
        __syncthreads();

        // S = Q @ K^T
        float sacc[16][4];
        #pragma unroll
        for (int i = 0; i < 16; i++)
            #pragma unroll
            for (int r = 0; r < 4; r++) sacc[i][r] = 0.f;
        #pragma unroll
        for (int kk = 0; kk < 8; kk++) {
            #pragma unroll
            for (int ni = 0; ni < 16; ni++) {
                const float* bp = Ks + (ni * 8 + g) * 68 + kk * 8 + l4;
                uint32_t bf[2] = { f2tf32(bp[0]), f2tf32(bp[4]) };
                mma8(sacc[ni], qf[kk], bf);
            }
        }

        // mask + scale + rowmax
        float mx0 = FNEG, mx1 = FNEG;
        #pragma unroll
        for (int ni = 0; ni < 16; ni++) {
            int col = ni * 8 + 2 * l4;
            int wI = (kt << 2) + (col >> 5), bI = col & 31;
            unsigned mwA = mskS[rA * 16 + wI];
            unsigned mwB = mskS[rB * 16 + wI];
            float v0 = ((mwA >> bI) & 1u)       ? sacc[ni][0] * 0.125f : FNEG;
            float v1 = ((mwA >> (bI + 1)) & 1u) ? sacc[ni][1] * 0.125f : FNEG;
            float v2 = ((mwB >> bI) & 1u)       ? sacc[ni][2] * 0.125f : FNEG;
            float v3 = ((mwB >> (bI + 1)) & 1u) ? sacc[ni][3] * 0.125f : FNEG;
            sacc[ni][0] = v0; sacc[ni][1] = v1; sacc[ni][2] = v2; sacc[ni][3] = v3;
            mx0 = fmaxf(mx0, fmaxf(v0, v1));
            mx1 = fmaxf(mx1, fmaxf(v2, v3));
        }
        mx0 = fmaxf(mx0, __shfl_xor_sync(0xffffffffu, mx0, 1));
        mx0 = fmaxf(mx0, __shfl_xor_sync(0xffffffffu, mx0, 2));
        mx1 = fmaxf(mx1, __shfl_xor_sync(0xffffffffu, mx1, 1));
        mx1 = fmaxf(mx1, __shfl_xor_sync(0xffffffffu, mx1, 2));

        float mn0 = fmaxf(mrow0, mx0), mn1 = fmaxf(mrow1, mx1);
        float al0 = expf(mrow0 - mn0), al1 = expf(mrow1 - mn1);
        float pvd0 = (mn0 > -1e29f) ? 1.f : 0.f;
        float pvd1 = (mn1 > -1e29f) ? 1.f : 0.f;

        float ps0 = 0.f, ps1 = 0.f;
        #pragma unroll
        for (int ni = 0; ni < 16; ni++) {
            float p0 = expf(sacc[ni][0] - mn0) * pvd0;
            float p1 = expf(sacc[ni][1] - mn0) * pvd0;
            float p2 = expf(sacc[ni][2] - mn1) * pvd1;
            float p3 = expf(sacc[ni][3] - mn1) * pvd1;
            ps0 += p0 + p1; ps1 += p2 + p3;
            int col = ni * 8 + 2 * l4;
            *(float2*)&Ps[rA * 132 + col] = make_float2(p0, p1);
            *(float2*)&Ps[rB * 132 + col] = make_float2(p2, p3);
        }
        ps0 += __shfl_xor_sync(0xffffffffu, ps0, 1);
        ps0 += __shfl_xor_sync(0xffffffffu, ps0, 2);
        ps1 += __shfl_xor_sync(0xffffffffu, ps1, 1);
        ps1 += __shfl_xor_sync(0xffffffffu, ps1, 2);
        lrow0 = lrow0 * al0 + ps0;
        lrow1 = lrow1 * al1 + ps1;
        mrow0 = mn0; mrow1 = mn1;
        #pragma unroll
        for (int i = 0; i < 8; i++) {
            oacc[i][0] *= al0; oacc[i][1] *= al0;
            oacc[i][2] *= al1; oacc[i][3] *= al1;
        }

        asm volatile("cp.async.wait_group 0;" ::: "memory");  // VT ready
        __syncthreads();

        // O += P @ V  (A from Ps, B from VTs)
        #pragma unroll
        for (int kk = 0; kk < 16; kk++) {
            const int kb = kk * 8 + l4;
            uint32_t af[4] = { f2tf32(Ps[rA * 132 + kb]), f2tf32(Ps[rB * 132 + kb]),
                               f2tf32(Ps[rA * 132 + kb + 4]), f2tf32(Ps[rB * 132 + kb + 4]) };
            #pragma unroll
            for (int ni = 0; ni < 8; ni++) {
                const float* bp = VTs + (ni * 8 + g) * 132 + kb;
                uint32_t bf[2] = { f2tf32(bp[0]), f2tf32(bp[4]) };
                mma8(oacc[ni], af, bf);
            }
        }
        __syncthreads();  // all warps done with Ks/VTs before next tile load
    }

    // epilogue: O /= l, write to g_attout
    const float inv0 = 1.f / lrow0, inv1 = 1.f / lrow1;
    float* OA = g_attout + (size_t)(qrow0 + rA) * DIM_ + h * 64;
    float* OB = g_attout + (size_t)(qrow0 + rB) * DIM_ + h * 64;
    #pragma unroll
    for (int ni = 0; ni < 8; ni++) {
        int col = ni * 8 + 2 * l4;
        *(float2*)&OA[col] = make_float2(oacc[ni][0] * inv0, oacc[ni][1] * inv0);
        *(float2*)&OB[col] = make_float2(oacc[ni][2] * inv1, oacc[ni][3] * inv1);
    }
}

// ======================================================================
// fp32 SIMT idx projections (both Wq and Wk in one launch, N=256 concat).
// ======================================================================
#define SMS 68
__global__ void k_idxproj(const float* __restrict__ hs,
                          const float* __restrict__ Wq, const float* __restrict__ Wk)
{
    __shared__ float As[16 * SMS];
    __shared__ float Bs[16 * SMS];
    const int t  = threadIdx.x;
    const int tx = t & 15, ty = t >> 4;
    const int m0 = blockIdx.y * 64;
    const int n0 = blockIdx.x * 64;
    const float* B = (n0 < 128) ? Wq : Wk;
    float* C = (n0 < 128) ? g_qI : g_kI;
    const int nb = n0 & 127;

    const int lm = t >> 2;
    const int lk = (t & 3) << 2;
    const float* Ap = hs + (size_t)(m0 + lm) * DIM_ + lk;
    const float* Bp = B + (size_t)(nb + lm) * DIM_ + lk;
    float acc[4][4] = {};
    for (int k0 = 0; k0 < DIM_; k0 += 16) {
        float4 av = *(const float4*)(Ap + k0);
        float4 bv = *(const float4*)(Bp + k0);
        __syncthreads();
        As[(lk+0)*SMS+lm]=av.x; As[(lk+1)*SMS+lm]=av.y;
        As[(lk+2)*SMS+lm]=av.z; As[(lk+3)*SMS+lm]=av.w;
        Bs[(lk+0)*SMS+lm]=bv.x; Bs[(lk+1)*SMS+lm]=bv.y;
        Bs[(lk+2)*SMS+lm]=bv.z; Bs[(lk+3)*SMS+lm]=bv.w;
        __syncthreads();
        #pragma unroll
        for (int kk = 0; kk < 16; kk++) {
            float4 a = *(const float4*)&As[kk*SMS + (ty<<2)];
            float4 b = *(const float4*)&Bs[kk*SMS + (tx<<2)];
            float ar[4] = {a.x,a.y,a.z,a.w};
            float br[4] = {b.x,b.y,b.z,b.w};
            #pragma unroll
            for (int i=0;i<4;i++)
                #pragma unroll
                for (int j=0;j<4;j++)
                    acc[i][j] = fmaf(ar[i], br[j], acc[i][j]);
        }
    }
    #pragma unroll
    for (int i=0;i<4;i++){
        int m = m0 + (ty<<2) + i;
        #pragma unroll
        for (int j=0;j<4;j++)
            C[(size_t)m*128 + nb + (tx<<2) + j] = acc[i][j];
    }
}

// ======================================================================
// V transpose: g_vt[z][d][k] = V[img][k][h*64+d]
// ======================================================================
__global__ void k_vt()
{
    __shared__ float s[32][65];
    const int z = blockIdx.x, kb = blockIdx.y;
    const int img = z >> 4, h = z & 15;
    const int t = threadIdx.x;
    const float* V = g_qkv + (size_t)img * LI_ * 3072 + 2048 + h * 64;
    const int kk = t >> 6, d = t & 63;
    #pragma unroll
    for (int i = 0; i < 8; i++) {
        int k = kb * 32 + kk + i * 4;
        s[kk + i * 4][d] = V[(size_t)k * 3072 + d];
    }
    __syncthreads();
    float* out = g_vt + (size_t)z * (DH_ * LI_) + kb * 32;
    const int ko = t & 31, dw = t >> 5;
    #pragma unroll
    for (int i = 0; i < 8; i++) {
        int dd = dw + i * 8;
        out[(size_t)dd * LI_ + ko] = s[ko][dd];
    }
}

// ======================================================================
// RoPE: sincos computed once per (s,d), applied to all 16 heads.
// ======================================================================
__global__ void k_rope(const float* __restrict__ rope)
{
    __shared__ float cs[32], sns[32];
    int s = blockIdx.x;
    int t = threadIdx.x;
    if (t < 32) {
        float ang = rope[(size_t)s * 32 + t];
        cs[t] = cosf(ang);
        sns[t] = sinf(ang);
    }
    __syncthreads();
    int h = t >> 5, d = t & 31;
    float c = cs[d], sn = sns[d];
    float* q = g_qkv + (size_t)s * 3072 + h * 64;
    float* k = q + 1024;
    float q1 = q[d], q2 = q[d + 32];
    q[d]      = q1 * c - q2 * sn;
    q[d + 32] = q2 * c + q1 * sn;
    float k1 = k[d], k2 = k[d + 32];
    k[d]      = k1 * c - k2 * sn;
    k[d + 32] = k2 * c + k1 * sn;
}

// ======================================================================
// Index scores: one block per 4 consecutive queries (same image).
// Per-(q,k) arithmetic identical to the validated single-q version.
// ======================================================================
__global__ void k_idx_scores(const int* __restrict__ coords,
                             const float* __restrict__ W1g, const float* __restrict__ b1g,
                             const float* __restrict__ W2g, const float* __restrict__ b2g,
                             const float* __restrict__ rpe_table)
{
    const int qb  = blockIdx.x;       // 0..511
    const int img = qb >> 7;
    const int gq0 = qb * 4;
    const int base = img << 9;
    __shared__ float qrow[4][128];
    __shared__ float w1s[GH_ * IH_], w2s[IH_ * GH_], b1s[GH_], b2s[IH_];
    __shared__ float rpes[NBUCK_ * IH_];
    __shared__ int   poss[LI_];
    __shared__ int   posq[4];
    int t = threadIdx.x;
    for (int i = t; i < 512; i += 256)
        qrow[i >> 7][i & 127] = g_qI[(size_t)(gq0 + (i >> 7)) * 128 + (i & 127)];
    if (t < 32) w1s[t] = W1g[t];
    else if (t < 64) w2s[t - 32] = W2g[t - 32];
    else if (t < 72) b1s[t - 64] = b1g[t - 64];
    else if (t < 76) b2s[t - 72] = b2g[t - 72];
    else if (t >= 80 && t < 84) posq[t - 80] = coords[(size_t)(gq0 + t - 80) * 2 + 1];
    for (int i = t; i < NBUCK_ * IH_; i += 256) rpes[i] = rpe_table[i];
    for (int i = t; i < LI_; i += 256) poss[i] = coords[(size_t)(base + i) * 2 + 1];
    __syncthreads();

    for (int k = t; k < LI_; k += 256) {
        const float* krow = g_kI + (size_t)(base + k) * 128;
        float dot[4][8];
        #pragma unroll
        for (int h = 0; h < 8; h++) {
            float4 b0 = *(const float4*)&krow[h * 16 + 0];
            float4 b1 = *(const float4*)&krow[h * 16 + 4];
            float4 b2 = *(const float4*)&krow[h * 16 + 8];
            float4 b3 = *(const float4*)&krow[h * 16 + 12];
            #pragma unroll
            for (int q = 0; q < 4; q++) {
                float s = 0.f;
                float4 a;
                a = *(const float4*)&qrow[q][h * 16 + 0];
                s += a.x*b0.x + a.y*b0.y + a.z*b0.z + a.w*b0.w;
                a = *(const float4*)&qrow[q][h * 16 + 4];
                s += a.x*b1.x + a.y*b1.y + a.z*b1.z + a.w*b1.w;
                a = *(const float4*)&qrow[q][h * 16 + 8];
                s += a.x*b2.x + a.y*b2.y + a.z*b2.z + a.w*b2.w;
                a = *(const float4*)&qrow[q][h * 16 + 12];
                s += a.x*b3.x + a.y*b3.y + a.z*b3.z + a.w*b3.w;
                dot[q][h] = s;
            }
        }
        #pragma unroll
        for (int q = 0; q < 4; q++) {
            int rel = posq[q] - poss[k];
            rel = rel < -64 ? -64 : (rel > 64 ? 64 : rel);
            const float* rp = &rpes[(rel + 64) * IH_];
            float xg[IH_];
            #pragma unroll
            for (int i = 0; i < IH_; i++) xg[i] = dot[q][IH_ + i] + rp[i];
            float hg[GH_];
            #pragma unroll
            for (int j = 0; j < GH_; j++) {
                float s = b1s[j];
                #pragma unroll
                for (int i = 0; i < IH_; i++) s = fmaf(w1s[j * IH_ + i], xg[i], s);
                hg[j] = fmaxf(s, 0.f);
            }
            float score = 0.f;
            #pragma unroll
            for (int i = 0; i < IH_; i++) {
                float s = b2s[i];
                #pragma unroll
                for (int j = 0; j < GH_; j++) s = fmaf(w2s[i * GH_ + j], hg[j], s);
                float gi = 1.f / (1.f + expf(-s));
                float rs = fmaxf(dot[q][i] + rp[i], 0.f);
                score = fmaf(rs, gi, score);
            }
            g_scores[(size_t)img * LI_ * LI_ + (size_t)(gq0 - base + q) * LI_ + k] = score;
        }
    }
}

// ======================================================================
// Exact top-K (K=256 of 512) per query row via 4-pass radix select.
// ======================================================================
__global__ void k_topk()
{
    int row  = blockIdx.x;
    int img  = row >> 9;
    const float* sc = g_scores + (size_t)img * LI_ * LI_ + (size_t)(row & 511) * LI_;
    __shared__ unsigned skeys[LI_];
    __shared__ unsigned hist[256];
    __shared__ unsigned mwords[16];
    __shared__ unsigned short eqidx[LI_];
    __shared__ unsigned s_prefix, s_kth, s_eqcnt;
    int t = threadIdx.x;

    for (int i = t; i < LI_; i += 256) {
        unsigned u = __float_as_uint(sc[i]);
        u = (u & 0x80000000u) ? ~u : (u | 0x80000000u);
        skeys[i] = u;
    }
    if (t == 0) { s_prefix = 0; s_kth = KSEL_; s_eqcnt = 0; }
    if (t < 16) mwords[t] = 0;
    __syncthreads();

    unsigned prefmask = 0;
    for (int r = 0; r < 4; r++) {
        int shift = 24 - 8 * r;
        for (int i = t; i < 256; i += 256) hist[i] = 0;
        __syncthreads();
        unsigned pref = s_prefix;
        for (int i = t; i < LI_; i += 256) {
            unsigned u = skeys[i];
            if ((u & prefmask) == pref) atomicAdd(&hist[(u >> shift) & 255], 1u);
        }
        __syncthreads();
        if (t == 0) {
            unsigned kth = s_kth, cum = 0;
            int b = 255;
            for (; b >= 0; b--) { cum += hist[b]; if (cum >= kth) break; }
            s_kth    = kth - (cum - hist[b]);
            s_prefix = pref | ((unsigned)b << shift);
        }
        prefmask |= (0xFFu << shift);
        __syncthreads();
    }
    unsigned tau = s_prefix;

    for (int i = t; i < LI_; i += 256) {
        unsigned u = skeys[i];
        if (u > tau) {
            atomicOr(&mwords[i >> 5], 1u << (i & 31));
        } else if (u == tau) {
            unsigned p = atomicAdd(&s_eqcnt, 1u);
            eqidx[p] = (unsigned short)i;
        }
    }
    __syncthreads();
    if (t == 0) {
        int cg = 0;
        #pragma unroll
        for (int w = 0; w < 16; w++) cg += __popc(mwords[w]);
        int need = KSEL_ - cg;
        int ce = (int)s_eqcnt;
        if (need > 0) {
            if (ce <= need) {
                for (int j = 0; j < ce; j++) { int i = eqidx[j]; mwords[i >> 5] |= 1u << (i & 31); }
            } else {
                for (int a = 1; a < ce; a++) {
                    unsigned short v = eqidx[a]; int b = a - 1;
                    while (b >= 0 && eqidx[b] > v) { eqidx[b + 1] = eqidx[b]; b--; }
                    eqidx[b + 1] = v;
                }
                for (int j = 0; j < need; j++) { int i = eqidx[j]; mwords[i >> 5] |= 1u << (i & 31); }
            }
        }
    }
    __syncthreads();
    if (t < 16) g_selmask[(size_t)row * 16 + t] = mwords[t];
}

// ======================================================================
// Launch
// ======================================================================
extern "C" void kernel_launch(void* const* d_in, const int* in_sizes, int n_in,
                              void* d_out, int out_size)
{
    const float* hs     = (const float*)d_in[0];
    const int*   coords = (const int*)  d_in[1];
    const float* rope   = (const float*)d_in[3];
    const float* Wq_idx = (const float*)d_in[4];
    const float* Wk_idx = (const float*)d_in[5];
    const float* W1g    = (const float*)d_in[6];
    const float* b1g    = (const float*)d_in[7];
    const float* W2g    = (const float*)d_in[8];
    const float* b2g    = (const float*)d_in[9];
    const float* rpe    = (const float*)d_in[10];
    const float* Wqkv_d = (const float*)d_in[11];
    const float* bqkv_d = (const float*)d_in[12];
    const float* Wqkv_u = (const float*)d_in[13];
    const float* bqkv_u = (const float*)d_in[14];
    const float* Wp_d   = (const float*)d_in[15];
    const float* bp_d   = (const float*)d_in[16];
    const float* Wp_u   = (const float*)d_in[17];
    const float* bp_u   = (const float*)d_in[18];
    const float* scaler = (const float*)d_in[19];
    float* out = (float*)d_out;

    float *tmp1, *qkv, *attout, *tmp2;
    cudaGetSymbolAddress((void**)&tmp1,   g_tmp1);
    cudaGetSymbolAddress((void**)&qkv,    g_qkv);
    cudaGetSymbolAddress((void**)&attout, g_attout);
    cudaGetSymbolAddress((void**)&tmp2,   g_tmp2);

    const int dyn128 = (2 * 128 + 2 * 128) * AST * 4;
    const int dyn64  = (2 * 128 + 2 * 64)  * AST * 4;
    const int dynFl  = (128*68 + 128*68 + 64*132 + 128*132) * 4 + 128 * 16 * 4; // 179200
    cudaFuncSetAttribute((const void*)k_mma_gemm<128,2,4>, cudaFuncAttributeMaxDynamicSharedMemorySize, dyn128);
    cudaFuncSetAttribute((const void*)k_mma_gemm<64,4,2>,  cudaFuncAttributeMaxDynamicSharedMemorySize, dyn64);
    cudaFuncSetAttribute((const void*)k_flash, cudaFuncAttributeMaxDynamicSharedMemorySize, dynFl);

    // qkv = (hs @ Wqkv_d.T + b) @ Wqkv_u.T + b
    k_mma_gemm<64,4,2><<<dim3(4, 16), 256, dyn64>>>(
        hs, DIM_, Wqkv_d, DIM_, tmp1, BOT_, DIM_, bqkv_d, nullptr);
    k_mma_gemm<128,2,4><<<dim3(24, 16), 256, dyn128>>>(
        tmp1, BOT_, Wqkv_u, BOT_, qkv, 3 * DIM_, BOT_, bqkv_u, nullptr);

    // V^T + RoPE (independent of each other: rope touches q,k only)
    k_vt<<<dim3(NIMG_ * H_, 16), 256>>>();
    k_rope<<<S_, 512>>>(rope);

    // index projections (fp32 SIMT, both weights, 128 blocks)
    k_idxproj<<<dim3(4, 32), 256>>>(hs, Wq_idx, Wk_idx);

    // index scores + exact top-K mask
    k_idx_scores<<<512, 256>>>(coords, W1g, b1g, W2g, b2g, rpe);
    k_topk<<<S_, 256>>>();

    // fused attention
    k_flash<<<dim3(4, NIMG_ * H_), 256, dynFl>>>();

    // final projection (+ scaler)
    k_mma_gemm<64,4,2><<<dim3(4, 16), 256, dyn64>>>(
        attout, DIM_, Wp_d, DIM_, tmp2, BOT_, DIM_, bp_d, nullptr);
    k_mma_gemm<128,2,4><<<dim3(8, 16), 256, dyn128>>>(
        tmp2, BOT_, Wp_u, BOT_, out, DIM_, BOT_, bp_u, scaler);
}